// round 5
// baseline (speedup 1.0000x reference)
#include <cuda_runtime.h>
#include <cstdint>
#include <cstddef>

#define Bdim 256
#define Ndim 256
#define Hdim 256
#define Fdim 64

// smem layout (floats): hS 32768 | stg 24576 | b1S 256 | b2S 64
#define SMEM_FLOATS (32768 + 24576 + 256 + 64)
#define SMEM_BYTES  (SMEM_FLOATS * 4)

// Q scratch: (B, N, F) fp32 = 16.8 MB
__device__ float g_Q[(size_t)Bdim * Ndim * Fdim];

// ---------------------------------------------------------------------------
// helpers
// ---------------------------------------------------------------------------
__device__ __forceinline__ uint32_t f2tf(float x) {
    uint32_t r;
    asm("cvt.rna.tf32.f32 %0, %1;" : "=r"(r) : "f"(x));
    return r;
}

__device__ __forceinline__ void mma8(float d[4], const uint32_t a[4], const uint32_t b[2]) {
    asm volatile(
        "mma.sync.aligned.m16n8k8.row.col.f32.tf32.tf32.f32 "
        "{%0,%1,%2,%3}, {%4,%5,%6,%7}, {%8,%9}, {%0,%1,%2,%3};"
        : "+f"(d[0]), "+f"(d[1]), "+f"(d[2]), "+f"(d[3])
        : "r"(a[0]), "r"(a[1]), "r"(a[2]), "r"(a[3]), "r"(b[0]), "r"(b[1]));
}

__device__ __forceinline__ void cp16(float* dst, const float* src) {
    uint32_t d = (uint32_t)__cvta_generic_to_shared(dst);
    asm volatile("cp.async.cg.shared.global [%0], [%1], 16;" :: "r"(d), "l"(src));
}

// smem word-index helpers (XOR swizzles; fragment loads verified conflict-free)
// A stage: 128 rows x 32 cols (row = 128B); 16B chunk index XOR (row & 7)
__device__ __forceinline__ int AW(int m, int k) {
    return m * 32 + ((((k >> 2) ^ (m & 7)) << 2) | (k & 3));
}
// B stage: 32 rows x 256 cols (row = 1KB); chunk XOR ((k & 3) << 1)
__device__ __forceinline__ int BW(int k, int nn) {
    return k * 256 + ((((nn >> 2) ^ ((k & 3) << 1)) << 2) | (nn & 3));
}
// h: 128 rows x 256 cols; chunk XOR (row & 7)
__device__ __forceinline__ int HW(int m, int k) {
    return m * 256 + ((((k >> 2) ^ (m & 7)) << 2) | (k & 3));
}

// ---------------------------------------------------------------------------
// layer1: D(128x256) = src(128 x 32*nst) @ W1(32*nst x 256); +b1, relu,
// tf32-round, store to hS. Then prefetches W2 (256x64 -> pad-72 rows) into stg.
// Warps: 2(m) x 4(n); warp tile 64x64; acc[4][8][4].
// ---------------------------------------------------------------------------
__device__ void layer1(float* __restrict__ hS, float* __restrict__ stg,
                       const float* __restrict__ b1S,
                       const float* __restrict__ src0, const float* __restrict__ src1,
                       const float* __restrict__ W1, const float* __restrict__ W2,
                       int nst, int n, int b0)
{
    const int t = threadIdx.x;
    const int lane = t & 31, w = t >> 5;
    const int qid = lane >> 2, t4 = lane & 3;
    const int wm = (w >> 2) * 64, wn = (w & 3) * 64;

    float acc[4][8][4];
#pragma unroll
    for (int im = 0; im < 4; im++)
#pragma unroll
        for (int in = 0; in < 8; in++)
#pragma unroll
            for (int e = 0; e < 4; e++) acc[im][in][e] = 0.f;

    auto issue = [&](int s) {
        float* As = stg + (s & 1) * 12288;
        float* Bs = As + 4096;
        const float* src = (s < 8) ? src0 : src1;
        const int kl = (s & 7) * 32;
        // A tile: 128 rows x 32 floats = 1024 16B-chunks, 4 per thread
#pragma unroll
        for (int i = 0; i < 4; i++) {
            int c = t * 4 + i, m = c >> 3, j = c & 7;
            cp16(As + m * 32 + ((j ^ (m & 7)) << 2),
                 src + ((size_t)(b0 + m) * Ndim + n) * Hdim + kl + j * 4);
        }
        // B tile: 32 rows x 256 floats = 2048 chunks, 8 per thread
        const float* Wr = W1 + (size_t)s * 32 * Hdim;
#pragma unroll
        for (int i = 0; i < 8; i++) {
            int c = t * 8 + i, kk = c >> 6, j = c & 63;
            cp16(Bs + kk * 256 + ((j ^ ((kk & 3) << 1)) << 2),
                 Wr + (size_t)kk * Hdim + j * 4);
        }
        asm volatile("cp.async.commit_group;");
    };

    issue(0);
    for (int s = 0; s < nst; s++) {
        if (s + 1 < nst) {
            issue(s + 1);
            asm volatile("cp.async.wait_group 1;");
        } else {
            asm volatile("cp.async.wait_group 0;");
        }
        __syncthreads();
        const float* As = stg + (s & 1) * 12288;
        const float* Bs = As + 4096;
#pragma unroll
        for (int kk = 0; kk < 32; kk += 8) {
            uint32_t af[4][4], bf[8][2];
#pragma unroll
            for (int im = 0; im < 4; im++) {
                int r = wm + im * 16 + qid, c = kk + t4;
                af[im][0] = f2tf(As[AW(r, c)]);
                af[im][1] = f2tf(As[AW(r + 8, c)]);
                af[im][2] = f2tf(As[AW(r, c + 4)]);
                af[im][3] = f2tf(As[AW(r + 8, c + 4)]);
            }
#pragma unroll
            for (int in = 0; in < 8; in++) {
                int nn = wn + in * 8 + qid, k = kk + t4;
                bf[in][0] = f2tf(Bs[BW(k, nn)]);
                bf[in][1] = f2tf(Bs[BW(k + 4, nn)]);
            }
#pragma unroll
            for (int im = 0; im < 4; im++)
#pragma unroll
                for (int in = 0; in < 8; in++)
                    mma8(acc[im][in], af[im], bf[in]);
        }
        __syncthreads();   // also protects stg before W2 prefetch below
    }

    // Prefetch W2 (256 x 64 fp32) into stg, pad-72 rows; overlaps epilogue.
#pragma unroll
    for (int i = 0; i < 16; i++)
        cp16(stg + t * 72 + i * 4, W2 + (size_t)t * Fdim + i * 4);
    asm volatile("cp.async.commit_group;");

    // epilogue: bias + relu + tf32 round -> hS
#pragma unroll
    for (int im = 0; im < 4; im++) {
        int r = wm + im * 16 + qid;
#pragma unroll
        for (int in = 0; in < 8; in++) {
            int c = wn + in * 8 + t4 * 2;
            float* d = acc[im][in];
            hS[HW(r, c)]         = __uint_as_float(f2tf(fmaxf(d[0] + b1S[c], 0.f)));
            hS[HW(r, c + 1)]     = __uint_as_float(f2tf(fmaxf(d[1] + b1S[c + 1], 0.f)));
            hS[HW(r + 8, c)]     = __uint_as_float(f2tf(fmaxf(d[2] + b1S[c], 0.f)));
            hS[HW(r + 8, c + 1)] = __uint_as_float(f2tf(fmaxf(d[3] + b1S[c + 1], 0.f)));
        }
    }
    asm volatile("cp.async.wait_group 0;");
}

// ---------------------------------------------------------------------------
// layer2: D(128x64) = hS(128x256) @ W2s(256x64, pad-72). Warps 4(m) x 2(n).
// ---------------------------------------------------------------------------
__device__ void layer2(const float* __restrict__ hS, const float* __restrict__ Ws,
                       float acc2[2][4][4])
{
    const int t = threadIdx.x;
    const int lane = t & 31, w = t >> 5;
    const int qid = lane >> 2, t4 = lane & 3;
    const int wm = (w >> 1) * 32, wn = (w & 1) * 32;
#pragma unroll
    for (int im = 0; im < 2; im++)
#pragma unroll
        for (int in = 0; in < 4; in++)
#pragma unroll
            for (int e = 0; e < 4; e++) acc2[im][in][e] = 0.f;

#pragma unroll 4
    for (int kk = 0; kk < 256; kk += 8) {
        uint32_t af[2][4], bf[4][2];
#pragma unroll
        for (int im = 0; im < 2; im++) {
            int r = wm + im * 16 + qid, c = kk + t4;
            af[im][0] = __float_as_uint(hS[HW(r, c)]);   // already tf32-rounded
            af[im][1] = __float_as_uint(hS[HW(r + 8, c)]);
            af[im][2] = __float_as_uint(hS[HW(r, c + 4)]);
            af[im][3] = __float_as_uint(hS[HW(r + 8, c + 4)]);
        }
#pragma unroll
        for (int in = 0; in < 4; in++) {
            int nn = wn + in * 8 + qid, k = kk + t4;
            bf[in][0] = f2tf(Ws[k * 72 + nn]);
            bf[in][1] = f2tf(Ws[(k + 4) * 72 + nn]);
        }
#pragma unroll
        for (int im = 0; im < 2; im++)
#pragma unroll
            for (int in = 0; in < 4; in++)
                mma8(acc2[im][in], af[im], bf[in]);
    }
}

// ---------------------------------------------------------------------------
// fused per-(node, 128-batch-tile) kernel: V path then A path; Q = V + A
// ---------------------------------------------------------------------------
__global__ void __launch_bounds__(256, 1)
critic_gemm(const float* __restrict__ obs, const float* __restrict__ act,
            const float* __restrict__ VW1, const float* __restrict__ Vb1,
            const float* __restrict__ VW2, const float* __restrict__ Vb2,
            const float* __restrict__ AW1, const float* __restrict__ Ab1,
            const float* __restrict__ AW2, const float* __restrict__ Ab2)
{
    extern __shared__ float sm[];
    float* hS  = sm;
    float* stg = sm + 32768;
    float* b1S = sm + 32768 + 24576;
    float* b2S = b1S + 256;

    const int n  = (int)blockIdx.y;
    const int b0 = (int)blockIdx.x * 128;
    const int t  = threadIdx.x;
    const int lane = t & 31, w = t >> 5;
    const int qid = lane >> 2, t4 = lane & 3;
    const int wm2 = (w >> 1) * 32, wn2 = (w & 1) * 32;

    // ---- V path ----
    b1S[t] = Vb1[n * Hdim + t];
    if (t < Fdim) b2S[t] = Vb2[n * Fdim + t];
    __syncthreads();

    layer1(hS, stg, b1S, obs, obs,
           VW1 + (size_t)n * Hdim * Hdim, VW2 + (size_t)n * Hdim * Fdim, 8, n, b0);
    __syncthreads();

    float vacc[2][4][4];
    layer2(hS, stg, vacc);

    // write V (+b2) to Q scratch
#pragma unroll
    for (int im = 0; im < 2; im++)
#pragma unroll
        for (int in = 0; in < 4; in++) {
            int r = wm2 + im * 16 + qid;
            int c = wn2 + in * 8 + t4 * 2;
            size_t base0 = ((size_t)(b0 + r) * Ndim + n) * Fdim + c;
            size_t base1 = ((size_t)(b0 + r + 8) * Ndim + n) * Fdim + c;
            g_Q[base0]     = vacc[im][in][0] + b2S[c];
            g_Q[base0 + 1] = vacc[im][in][1] + b2S[c + 1];
            g_Q[base1]     = vacc[im][in][2] + b2S[c];
            g_Q[base1 + 1] = vacc[im][in][3] + b2S[c + 1];
        }
    __syncthreads();   // all stg/hS reads done before A path overwrites them

    // ---- A path ----
    b1S[t] = Ab1[n * Hdim + t];
    if (t < Fdim) b2S[t] = Ab2[n * Fdim + t];
    __syncthreads();

    layer1(hS, stg, b1S, obs, act,
           AW1 + (size_t)n * 2 * Hdim * Hdim, AW2 + (size_t)n * Hdim * Fdim, 16, n, b0);
    __syncthreads();

    float aacc[2][4][4];
    layer2(hS, stg, aacc);

    // Q = V + A (+b2): read-modify-write (same thread wrote these addresses)
#pragma unroll
    for (int im = 0; im < 2; im++)
#pragma unroll
        for (int in = 0; in < 4; in++) {
            int r = wm2 + im * 16 + qid;
            int c = wn2 + in * 8 + t4 * 2;
            size_t base0 = ((size_t)(b0 + r) * Ndim + n) * Fdim + c;
            size_t base1 = ((size_t)(b0 + r + 8) * Ndim + n) * Fdim + c;
            g_Q[base0]     += aacc[im][in][0] + b2S[c];
            g_Q[base0 + 1] += aacc[im][in][1] + b2S[c + 1];
            g_Q[base1]     += aacc[im][in][2] + b2S[c];
            g_Q[base1 + 1] += aacc[im][in][3] + b2S[c + 1];
        }
}

// ---------------------------------------------------------------------------
// final: subset mins over 4 neighbors (15 subsets), chi = sum_s w[n,s]*min_s,
// out[b,n] = mean_f(chi_f + Q[b, center(n), f]).
// block (64 f-lanes, 4 batches), grid (N, B/4). Handles int32 or int64 edges.
// ---------------------------------------------------------------------------
__global__ void critic_final(const float* __restrict__ chi_m,
                             const int* __restrict__ e32,
                             float* __restrict__ out)
{
    const int n  = (int)blockIdx.x;
    const int tx = threadIdx.x;            // 0..63 : feature
    const int ty = threadIdx.y;            // 0..3  : batch sub
    const int b  = (int)blockIdx.y * 4 + ty;
    const int t  = ty * 64 + tx;

    __shared__ float wS[15];
    __shared__ int   nd[5];
    __shared__ float part[8];

    // dtype detect: int32 layout -> word[5] = centers[1] = 1; int64 -> 0.
    const bool is64 = (e32[5] != 1);

    if (t < 15)
        wS[t] = (chi_m[(n * 3 + 0) * 15 + t] +
                 chi_m[(n * 3 + 1) * 15 + t] +
                 chi_m[(n * 3 + 2) * 15 + t]) * (1.f / 3.f);
    if (t < 5)
        nd[t] = is64 ? e32[n * 10 + 2 * t] : e32[n * 5 + t];
    __syncthreads();

    const float* Qb = g_Q + (size_t)b * (Ndim * Fdim);
    const float q0 = Qb[nd[1] * Fdim + tx];
    const float q1 = Qb[nd[2] * Fdim + tx];
    const float q2 = Qb[nd[3] * Fdim + tx];
    const float q3 = Qb[nd[4] * Fdim + tx];
    const float qc = Qb[nd[0] * Fdim + tx];

    // subset mins: subset value s (1..15), bit i selects neighbor i
    const float v3  = fminf(q0, q1);
    const float v5  = fminf(q0, q2);
    const float v6  = fminf(q1, q2);
    const float v7  = fminf(v3, q2);
    const float v9  = fminf(q0, q3);
    const float v10 = fminf(q1, q3);
    const float v11 = fminf(v3, q3);
    const float v12 = fminf(q2, q3);
    const float v13 = fminf(v5, q3);
    const float v14 = fminf(v6, q3);
    const float v15 = fminf(v7, q3);

    float chi = wS[0] * q0  + wS[1] * q1  + wS[2] * v3  + wS[3] * q2
              + wS[4] * v5  + wS[5] * v6  + wS[6] * v7  + wS[7] * q3
              + wS[8] * v9  + wS[9] * v10 + wS[10] * v11 + wS[11] * v12
              + wS[12] * v13 + wS[13] * v14 + wS[14] * v15;

    float r = (chi + qc) * (1.f / 64.f);
#pragma unroll
    for (int o = 16; o; o >>= 1)
        r += __shfl_xor_sync(0xffffffffu, r, o);

    const int warp = t >> 5;               // 0..7
    if ((t & 31) == 0) part[warp] = r;
    __syncthreads();
    if (tx == 0)
        out[b * Ndim + n] = part[ty * 2] + part[ty * 2 + 1];
}

// ---------------------------------------------------------------------------
extern "C" void kernel_launch(void* const* d_in, const int* in_sizes, int n_in,
                              void* d_out, int out_size)
{
    const float* obs = (const float*)d_in[0];
    const float* act = (const float*)d_in[1];
    const float* VW1 = (const float*)d_in[2];
    const float* Vb1 = (const float*)d_in[3];
    const float* VW2 = (const float*)d_in[4];
    const float* Vb2 = (const float*)d_in[5];
    const float* AW1 = (const float*)d_in[6];
    const float* Ab1 = (const float*)d_in[7];
    const float* AW2 = (const float*)d_in[8];
    const float* Ab2 = (const float*)d_in[9];
    const float* chi = (const float*)d_in[10];
    const int*   edg = (const int*)d_in[11];

    cudaFuncSetAttribute(critic_gemm,
                         cudaFuncAttributeMaxDynamicSharedMemorySize, SMEM_BYTES);

    critic_gemm<<<dim3(Bdim / 128, Ndim), 256, SMEM_BYTES>>>(
        obs, act, VW1, Vb1, VW2, Vb2, AW1, Ab1, AW2, Ab2);

    critic_final<<<dim3(Ndim, Bdim / 4), dim3(64, 4)>>>(
        chi, edg, (float*)d_out);
}

// round 6
// speedup vs baseline: 1.0001x; 1.0001x over previous
#include <cuda_runtime.h>
#include <cstdint>
#include <cstddef>

#define Bdim 256
#define Ndim 256
#define Hdim 256
#define Fdim 64

// smem layout (floats): hS 32768 | stg 24576 | b1S 256 | b2S 64
#define SMEM_FLOATS (32768 + 24576 + 256 + 64)
#define SMEM_BYTES  (SMEM_FLOATS * 4)

// Q scratch: (B, N, F) fp32 = 16.8 MB
__device__ float g_Q[(size_t)Bdim * Ndim * Fdim];

// ---------------------------------------------------------------------------
// helpers
// ---------------------------------------------------------------------------
__device__ __forceinline__ uint32_t f2tf(float x) {
    uint32_t r;
    asm("cvt.rna.tf32.f32 %0, %1;" : "=r"(r) : "f"(x));
    return r;
}

__device__ __forceinline__ void mma8(float d[4], const uint32_t a[4], const uint32_t b[2]) {
    asm volatile(
        "mma.sync.aligned.m16n8k8.row.col.f32.tf32.tf32.f32 "
        "{%0,%1,%2,%3}, {%4,%5,%6,%7}, {%8,%9}, {%0,%1,%2,%3};"
        : "+f"(d[0]), "+f"(d[1]), "+f"(d[2]), "+f"(d[3])
        : "r"(a[0]), "r"(a[1]), "r"(a[2]), "r"(a[3]), "r"(b[0]), "r"(b[1]));
}

__device__ __forceinline__ void cp16(float* dst, const float* src) {
    uint32_t d = (uint32_t)__cvta_generic_to_shared(dst);
    asm volatile("cp.async.cg.shared.global [%0], [%1], 16;" :: "r"(d), "l"(src));
}

// smem word-index helpers (XOR swizzles; fragment loads verified conflict-free)
// A stage: 128 rows x 32 cols (row = 128B); 16B chunk index XOR (row & 7)
__device__ __forceinline__ int AW(int m, int k) {
    return m * 32 + ((((k >> 2) ^ (m & 7)) << 2) | (k & 3));
}
// B stage: 32 rows x 256 cols (row = 1KB); chunk XOR ((k & 3) << 1)
__device__ __forceinline__ int BW(int k, int nn) {
    return k * 256 + ((((nn >> 2) ^ ((k & 3) << 1)) << 2) | (nn & 3));
}
// h: 128 rows x 256 cols; chunk XOR (row & 7)
__device__ __forceinline__ int HW(int m, int k) {
    return m * 256 + ((((k >> 2) ^ (m & 7)) << 2) | (k & 3));
}

// ---------------------------------------------------------------------------
// layer1: D(128x256) = src(128 x 32*nst) @ W1(32*nst x 256); +b1, relu,
// tf32-round, store to hS. Then prefetches W2 (256x64 -> pad-72 rows) into stg.
// Warps: 2(m) x 4(n); warp tile 64x64; acc[4][8][4].
// ---------------------------------------------------------------------------
__device__ void layer1(float* __restrict__ hS, float* __restrict__ stg,
                       const float* __restrict__ b1S,
                       const float* __restrict__ src0, const float* __restrict__ src1,
                       const float* __restrict__ W1, const float* __restrict__ W2,
                       int nst, int n, int b0)
{
    const int t = threadIdx.x;
    const int lane = t & 31, w = t >> 5;
    const int qid = lane >> 2, t4 = lane & 3;
    const int wm = (w >> 2) * 64, wn = (w & 3) * 64;

    float acc[4][8][4];
#pragma unroll
    for (int im = 0; im < 4; im++)
#pragma unroll
        for (int in = 0; in < 8; in++)
#pragma unroll
            for (int e = 0; e < 4; e++) acc[im][in][e] = 0.f;

    auto issue = [&](int s) {
        float* As = stg + (s & 1) * 12288;
        float* Bs = As + 4096;
        const float* src = (s < 8) ? src0 : src1;
        const int kl = (s & 7) * 32;
        // A tile: 128 rows x 32 floats = 1024 16B-chunks, 4 per thread
#pragma unroll
        for (int i = 0; i < 4; i++) {
            int c = t * 4 + i, m = c >> 3, j = c & 7;
            cp16(As + m * 32 + ((j ^ (m & 7)) << 2),
                 src + ((size_t)(b0 + m) * Ndim + n) * Hdim + kl + j * 4);
        }
        // B tile: 32 rows x 256 floats = 2048 chunks, 8 per thread
        const float* Wr = W1 + (size_t)s * 32 * Hdim;
#pragma unroll
        for (int i = 0; i < 8; i++) {
            int c = t * 8 + i, kk = c >> 6, j = c & 63;
            cp16(Bs + kk * 256 + ((j ^ ((kk & 3) << 1)) << 2),
                 Wr + (size_t)kk * Hdim + j * 4);
        }
        asm volatile("cp.async.commit_group;");
    };

    issue(0);
    for (int s = 0; s < nst; s++) {
        if (s + 1 < nst) {
            issue(s + 1);
            asm volatile("cp.async.wait_group 1;");
        } else {
            asm volatile("cp.async.wait_group 0;");
        }
        __syncthreads();
        const float* As = stg + (s & 1) * 12288;
        const float* Bs = As + 4096;
#pragma unroll
        for (int kk = 0; kk < 32; kk += 8) {
            uint32_t af[4][4], bf[8][2];
#pragma unroll
            for (int im = 0; im < 4; im++) {
                int r = wm + im * 16 + qid, c = kk + t4;
                af[im][0] = f2tf(As[AW(r, c)]);
                af[im][1] = f2tf(As[AW(r + 8, c)]);
                af[im][2] = f2tf(As[AW(r, c + 4)]);
                af[im][3] = f2tf(As[AW(r + 8, c + 4)]);
            }
#pragma unroll
            for (int in = 0; in < 8; in++) {
                int nn = wn + in * 8 + qid, k = kk + t4;
                bf[in][0] = f2tf(Bs[BW(k, nn)]);
                bf[in][1] = f2tf(Bs[BW(k + 4, nn)]);
            }
#pragma unroll
            for (int im = 0; im < 4; im++)
#pragma unroll
                for (int in = 0; in < 8; in++)
                    mma8(acc[im][in], af[im], bf[in]);
        }
        __syncthreads();   // also protects stg before W2 prefetch below
    }

    // Prefetch W2 (256 x 64 fp32) into stg, pad-72 rows; overlaps epilogue.
#pragma unroll
    for (int i = 0; i < 16; i++)
        cp16(stg + t * 72 + i * 4, W2 + (size_t)t * Fdim + i * 4);
    asm volatile("cp.async.commit_group;");

    // epilogue: bias + relu + tf32 round -> hS
#pragma unroll
    for (int im = 0; im < 4; im++) {
        int r = wm + im * 16 + qid;
#pragma unroll
        for (int in = 0; in < 8; in++) {
            int c = wn + in * 8 + t4 * 2;
            float* d = acc[im][in];
            hS[HW(r, c)]         = __uint_as_float(f2tf(fmaxf(d[0] + b1S[c], 0.f)));
            hS[HW(r, c + 1)]     = __uint_as_float(f2tf(fmaxf(d[1] + b1S[c + 1], 0.f)));
            hS[HW(r + 8, c)]     = __uint_as_float(f2tf(fmaxf(d[2] + b1S[c], 0.f)));
            hS[HW(r + 8, c + 1)] = __uint_as_float(f2tf(fmaxf(d[3] + b1S[c + 1], 0.f)));
        }
    }
    asm volatile("cp.async.wait_group 0;");
}

// ---------------------------------------------------------------------------
// layer2: D(128x64) = hS(128x256) @ W2s(256x64, pad-72). Warps 4(m) x 2(n).
// ---------------------------------------------------------------------------
__device__ void layer2(const float* __restrict__ hS, const float* __restrict__ Ws,
                       float acc2[2][4][4])
{
    const int t = threadIdx.x;
    const int lane = t & 31, w = t >> 5;
    const int qid = lane >> 2, t4 = lane & 3;
    const int wm = (w >> 1) * 32, wn = (w & 1) * 32;
#pragma unroll
    for (int im = 0; im < 2; im++)
#pragma unroll
        for (int in = 0; in < 4; in++)
#pragma unroll
            for (int e = 0; e < 4; e++) acc2[im][in][e] = 0.f;

#pragma unroll 4
    for (int kk = 0; kk < 256; kk += 8) {
        uint32_t af[2][4], bf[4][2];
#pragma unroll
        for (int im = 0; im < 2; im++) {
            int r = wm + im * 16 + qid, c = kk + t4;
            af[im][0] = __float_as_uint(hS[HW(r, c)]);   // already tf32-rounded
            af[im][1] = __float_as_uint(hS[HW(r + 8, c)]);
            af[im][2] = __float_as_uint(hS[HW(r, c + 4)]);
            af[im][3] = __float_as_uint(hS[HW(r + 8, c + 4)]);
        }
#pragma unroll
        for (int in = 0; in < 4; in++) {
            int nn = wn + in * 8 + qid, k = kk + t4;
            bf[in][0] = f2tf(Ws[k * 72 + nn]);
            bf[in][1] = f2tf(Ws[(k + 4) * 72 + nn]);
        }
#pragma unroll
        for (int im = 0; im < 2; im++)
#pragma unroll
            for (int in = 0; in < 4; in++)
                mma8(acc2[im][in], af[im], bf[in]);
    }
}

// ---------------------------------------------------------------------------
// fused per-(node, 128-batch-tile) kernel: V path then A path; Q = V + A
// ---------------------------------------------------------------------------
__global__ void __launch_bounds__(256, 1)
critic_gemm(const float* __restrict__ obs, const float* __restrict__ act,
            const float* __restrict__ VW1, const float* __restrict__ Vb1,
            const float* __restrict__ VW2, const float* __restrict__ Vb2,
            const float* __restrict__ AW1, const float* __restrict__ Ab1,
            const float* __restrict__ AW2, const float* __restrict__ Ab2)
{
    extern __shared__ float sm[];
    float* hS  = sm;
    float* stg = sm + 32768;
    float* b1S = sm + 32768 + 24576;
    float* b2S = b1S + 256;

    const int n  = (int)blockIdx.y;
    const int b0 = (int)blockIdx.x * 128;
    const int t  = threadIdx.x;
    const int lane = t & 31, w = t >> 5;
    const int qid = lane >> 2, t4 = lane & 3;
    const int wm2 = (w >> 1) * 32, wn2 = (w & 1) * 32;

    // ---- V path ----
    b1S[t] = Vb1[n * Hdim + t];
    if (t < Fdim) b2S[t] = Vb2[n * Fdim + t];
    __syncthreads();

    layer1(hS, stg, b1S, obs, obs,
           VW1 + (size_t)n * Hdim * Hdim, VW2 + (size_t)n * Hdim * Fdim, 8, n, b0);
    __syncthreads();

    float vacc[2][4][4];
    layer2(hS, stg, vacc);

    // write V (+b2) to Q scratch
#pragma unroll
    for (int im = 0; im < 2; im++)
#pragma unroll
        for (int in = 0; in < 4; in++) {
            int r = wm2 + im * 16 + qid;
            int c = wn2 + in * 8 + t4 * 2;
            size_t base0 = ((size_t)(b0 + r) * Ndim + n) * Fdim + c;
            size_t base1 = ((size_t)(b0 + r + 8) * Ndim + n) * Fdim + c;
            g_Q[base0]     = vacc[im][in][0] + b2S[c];
            g_Q[base0 + 1] = vacc[im][in][1] + b2S[c + 1];
            g_Q[base1]     = vacc[im][in][2] + b2S[c];
            g_Q[base1 + 1] = vacc[im][in][3] + b2S[c + 1];
        }
    __syncthreads();   // all stg/hS reads done before A path overwrites them

    // ---- A path ----
    b1S[t] = Ab1[n * Hdim + t];
    if (t < Fdim) b2S[t] = Ab2[n * Fdim + t];
    __syncthreads();

    layer1(hS, stg, b1S, obs, act,
           AW1 + (size_t)n * 2 * Hdim * Hdim, AW2 + (size_t)n * Hdim * Fdim, 16, n, b0);
    __syncthreads();

    float aacc[2][4][4];
    layer2(hS, stg, aacc);

    // Q = V + A (+b2): read-modify-write (same thread wrote these addresses)
#pragma unroll
    for (int im = 0; im < 2; im++)
#pragma unroll
        for (int in = 0; in < 4; in++) {
            int r = wm2 + im * 16 + qid;
            int c = wn2 + in * 8 + t4 * 2;
            size_t base0 = ((size_t)(b0 + r) * Ndim + n) * Fdim + c;
            size_t base1 = ((size_t)(b0 + r + 8) * Ndim + n) * Fdim + c;
            g_Q[base0]     += aacc[im][in][0] + b2S[c];
            g_Q[base0 + 1] += aacc[im][in][1] + b2S[c + 1];
            g_Q[base1]     += aacc[im][in][2] + b2S[c];
            g_Q[base1 + 1] += aacc[im][in][3] + b2S[c + 1];
        }
}

// ---------------------------------------------------------------------------
// final: subset mins over 4 neighbors (15 subsets), chi = sum_s w[n,s]*min_s,
// out[b,n] = mean_f(chi_f + Q[b, center(n), f]).
// block (64 f-lanes, 4 batches), grid (N, B/4). Handles int32 or int64 edges.
// ---------------------------------------------------------------------------
__global__ void critic_final(const float* __restrict__ chi_m,
                             const int* __restrict__ e32,
                             float* __restrict__ out)
{
    const int n  = (int)blockIdx.x;
    const int tx = threadIdx.x;            // 0..63 : feature
    const int ty = threadIdx.y;            // 0..3  : batch sub
    const int b  = (int)blockIdx.y * 4 + ty;
    const int t  = ty * 64 + tx;

    __shared__ float wS[15];
    __shared__ int   nd[5];
    __shared__ float part[8];

    // dtype detect: int32 layout -> word[5] = centers[1] = 1; int64 -> 0.
    const bool is64 = (e32[5] != 1);

    if (t < 15)
        wS[t] = (chi_m[(n * 3 + 0) * 15 + t] +
                 chi_m[(n * 3 + 1) * 15 + t] +
                 chi_m[(n * 3 + 2) * 15 + t]) * (1.f / 3.f);
    if (t < 5)
        nd[t] = is64 ? e32[n * 10 + 2 * t] : e32[n * 5 + t];
    __syncthreads();

    const float* Qb = g_Q + (size_t)b * (Ndim * Fdim);
    const float q0 = Qb[nd[1] * Fdim + tx];
    const float q1 = Qb[nd[2] * Fdim + tx];
    const float q2 = Qb[nd[3] * Fdim + tx];
    const float q3 = Qb[nd[4] * Fdim + tx];
    const float qc = Qb[nd[0] * Fdim + tx];

    // subset mins: subset value s (1..15), bit i selects neighbor i
    const float v3  = fminf(q0, q1);
    const float v5  = fminf(q0, q2);
    const float v6  = fminf(q1, q2);
    const float v7  = fminf(v3, q2);
    const float v9  = fminf(q0, q3);
    const float v10 = fminf(q1, q3);
    const float v11 = fminf(v3, q3);
    const float v12 = fminf(q2, q3);
    const float v13 = fminf(v5, q3);
    const float v14 = fminf(v6, q3);
    const float v15 = fminf(v7, q3);

    float chi = wS[0] * q0  + wS[1] * q1  + wS[2] * v3  + wS[3] * q2
              + wS[4] * v5  + wS[5] * v6  + wS[6] * v7  + wS[7] * q3
              + wS[8] * v9  + wS[9] * v10 + wS[10] * v11 + wS[11] * v12
              + wS[12] * v13 + wS[13] * v14 + wS[14] * v15;

    float r = (chi + qc) * (1.f / 64.f);
#pragma unroll
    for (int o = 16; o; o >>= 1)
        r += __shfl_xor_sync(0xffffffffu, r, o);

    const int warp = t >> 5;               // 0..7
    if ((t & 31) == 0) part[warp] = r;
    __syncthreads();
    if (tx == 0)
        out[b * Ndim + n] = part[ty * 2] + part[ty * 2 + 1];
}

// ---------------------------------------------------------------------------
extern "C" void kernel_launch(void* const* d_in, const int* in_sizes, int n_in,
                              void* d_out, int out_size)
{
    const float* obs = (const float*)d_in[0];
    const float* act = (const float*)d_in[1];
    const float* VW1 = (const float*)d_in[2];
    const float* Vb1 = (const float*)d_in[3];
    const float* VW2 = (const float*)d_in[4];
    const float* Vb2 = (const float*)d_in[5];
    const float* AW1 = (const float*)d_in[6];
    const float* Ab1 = (const float*)d_in[7];
    const float* AW2 = (const float*)d_in[8];
    const float* Ab2 = (const float*)d_in[9];
    const float* chi = (const float*)d_in[10];
    const int*   edg = (const int*)d_in[11];

    cudaFuncSetAttribute(critic_gemm,
                         cudaFuncAttributeMaxDynamicSharedMemorySize, SMEM_BYTES);

    critic_gemm<<<dim3(Bdim / 128, Ndim), 256, SMEM_BYTES>>>(
        obs, act, VW1, Vb1, VW2, Vb2, AW1, Ab1, AW2, Ab2);

    critic_final<<<dim3(Ndim, Bdim / 4), dim3(64, 4)>>>(
        chi, edg, (float*)d_out);
}

// round 8
// speedup vs baseline: 1.3506x; 1.3505x over previous
#include <cuda_runtime.h>
#include <cstdint>
#include <cstddef>

#define Bdim 256
#define Ndim 256
#define Hdim 256
#define Fdim 64

// smem layout (floats): hS 32768 | stg 24576 | b1S 256 | b2S 64
#define SMEM_FLOATS (32768 + 24576 + 256 + 64)
#define SMEM_BYTES  (SMEM_FLOATS * 4)

// Q scratch: (B, N, F) fp32 = 16.8 MB
__device__ float g_Q[(size_t)Bdim * Ndim * Fdim];

// ---------------------------------------------------------------------------
// helpers
// ---------------------------------------------------------------------------
__device__ __forceinline__ uint32_t f2tf(float x) {
    uint32_t r;
    asm("cvt.rna.tf32.f32 %0, %1;" : "=r"(r) : "f"(x));
    return r;
}

__device__ __forceinline__ void mma8(float d[4], const uint32_t a[4], const uint32_t b[2]) {
    asm volatile(
        "mma.sync.aligned.m16n8k8.row.col.f32.tf32.tf32.f32 "
        "{%0,%1,%2,%3}, {%4,%5,%6,%7}, {%8,%9}, {%0,%1,%2,%3};"
        : "+f"(d[0]), "+f"(d[1]), "+f"(d[2]), "+f"(d[3])
        : "r"(a[0]), "r"(a[1]), "r"(a[2]), "r"(a[3]), "r"(b[0]), "r"(b[1]));
}

__device__ __forceinline__ void cp16(float* dst, const float* src) {
    uint32_t d = (uint32_t)__cvta_generic_to_shared(dst);
    asm volatile("cp.async.cg.shared.global [%0], [%1], 16;" :: "r"(d), "l"(src));
}

// smem word-index helpers (XOR swizzles; fragment loads verified conflict-free)
// A stage: 128 rows x 32 cols (row = 128B); 16B chunk index XOR (row & 7)
__device__ __forceinline__ int AW(int m, int k) {
    return m * 32 + ((((k >> 2) ^ (m & 7)) << 2) | (k & 3));
}
// B stage: 32 rows x 256 cols (row = 1KB); chunk XOR ((k & 3) << 1)
__device__ __forceinline__ int BW(int k, int nn) {
    return k * 256 + ((((nn >> 2) ^ ((k & 3) << 1)) << 2) | (nn & 3));
}
// h: 128 rows x 256 cols; chunk XOR (row & 7)
__device__ __forceinline__ int HW(int m, int k) {
    return m * 256 + ((((k >> 2) ^ (m & 7)) << 2) | (k & 3));
}

// ---------------------------------------------------------------------------
// layer1: D(128x256) = src(128 x 32*nst) @ W1(32*nst x 256); +b1, relu,
// tf32-round, store to hS. Then prefetches W2 (256x64 -> pad-72 rows) into stg.
// Warps: 2(m) x 4(n); warp tile 64x64; acc[4][8][4].
// ---------------------------------------------------------------------------
__device__ void layer1(float* __restrict__ hS, float* __restrict__ stg,
                       const float* __restrict__ b1S,
                       const float* __restrict__ src0, const float* __restrict__ src1,
                       const float* __restrict__ W1, const float* __restrict__ W2,
                       int nst, int n, int b0)
{
    const int t = threadIdx.x;
    const int lane = t & 31, w = t >> 5;
    const int qid = lane >> 2, t4 = lane & 3;
    const int wm = (w >> 2) * 64, wn = (w & 3) * 64;

    float acc[4][8][4];
#pragma unroll
    for (int im = 0; im < 4; im++)
#pragma unroll
        for (int in = 0; in < 8; in++)
#pragma unroll
            for (int e = 0; e < 4; e++) acc[im][in][e] = 0.f;

    auto issue = [&](int s) {
        float* As = stg + (s & 1) * 12288;
        float* Bs = As + 4096;
        const float* src = (s < 8) ? src0 : src1;
        const int kl = (s & 7) * 32;
        // A tile: 128 rows x 8 chunks = 1024 chunks; thread t -> {t, 256+t, ...}
        // per (warp,i): 4 rows x 8 consecutive chunks -> coalesced 128B rows,
        // smem store = 4 phases (optimal)
#pragma unroll
        for (int i = 0; i < 4; i++) {
            int c = i * 256 + t, m = c >> 3, j = c & 7;
            cp16(As + m * 32 + ((j ^ (m & 7)) << 2),
                 src + ((size_t)(b0 + m) * Ndim + n) * Hdim + kl + j * 4);
        }
        // B tile: 32 rows x 64 chunks = 2048 chunks; thread t -> {t, 256+t, ...}
        // per (warp,i): one row, 32 consecutive chunks -> coalesced 512B,
        // smem store = 4 phases (optimal)
        const float* Wr = W1 + (size_t)s * 32 * Hdim;
#pragma unroll
        for (int i = 0; i < 8; i++) {
            int c = i * 256 + t, kk = c >> 6, j = c & 63;
            cp16(Bs + kk * 256 + ((j ^ ((kk & 3) << 1)) << 2),
                 Wr + (size_t)kk * Hdim + j * 4);
        }
        asm volatile("cp.async.commit_group;");
    };

    issue(0);
    for (int s = 0; s < nst; s++) {
        if (s + 1 < nst) {
            issue(s + 1);
            asm volatile("cp.async.wait_group 1;");
        } else {
            asm volatile("cp.async.wait_group 0;");
        }
        __syncthreads();
        const float* As = stg + (s & 1) * 12288;
        const float* Bs = As + 4096;
#pragma unroll
        for (int kk = 0; kk < 32; kk += 8) {
            uint32_t af[4][4], bf[8][2];
#pragma unroll
            for (int im = 0; im < 4; im++) {
                int r = wm + im * 16 + qid, c = kk + t4;
                af[im][0] = f2tf(As[AW(r, c)]);
                af[im][1] = f2tf(As[AW(r + 8, c)]);
                af[im][2] = f2tf(As[AW(r, c + 4)]);
                af[im][3] = f2tf(As[AW(r + 8, c + 4)]);
            }
#pragma unroll
            for (int in = 0; in < 8; in++) {
                int nn = wn + in * 8 + qid, k = kk + t4;
                bf[in][0] = f2tf(Bs[BW(k, nn)]);
                bf[in][1] = f2tf(Bs[BW(k + 4, nn)]);
            }
#pragma unroll
            for (int im = 0; im < 4; im++)
#pragma unroll
                for (int in = 0; in < 8; in++)
                    mma8(acc[im][in], af[im], bf[in]);
        }
        __syncthreads();   // protects stg before next issue / W2 prefetch
    }

    // Prefetch W2 (256 x 64 fp32) into stg, pad-72 rows; overlaps epilogue.
#pragma unroll
    for (int i = 0; i < 16; i++)
        cp16(stg + t * 72 + i * 4, W2 + (size_t)t * Fdim + i * 4);
    asm volatile("cp.async.commit_group;");

    // epilogue: bias + relu + tf32 round -> hS (float2: adjacent words in HW)
#pragma unroll
    for (int im = 0; im < 4; im++) {
        int r = wm + im * 16 + qid;
#pragma unroll
        for (int in = 0; in < 8; in++) {
            int c = wn + in * 8 + t4 * 2;
            float* d = acc[im][in];
            float2 v0, v1;
            v0.x = __uint_as_float(f2tf(fmaxf(d[0] + b1S[c], 0.f)));
            v0.y = __uint_as_float(f2tf(fmaxf(d[1] + b1S[c + 1], 0.f)));
            v1.x = __uint_as_float(f2tf(fmaxf(d[2] + b1S[c], 0.f)));
            v1.y = __uint_as_float(f2tf(fmaxf(d[3] + b1S[c + 1], 0.f)));
            *(float2*)(hS + HW(r, c))     = v0;
            *(float2*)(hS + HW(r + 8, c)) = v1;
        }
    }
    asm volatile("cp.async.wait_group 0;");
}

// ---------------------------------------------------------------------------
// layer2: D(128x64) = hS(128x256) @ W2s(256x64, pad-72). Warps 4(m) x 2(n).
// ---------------------------------------------------------------------------
__device__ void layer2(const float* __restrict__ hS, const float* __restrict__ Ws,
                       float acc2[2][4][4])
{
    const int t = threadIdx.x;
    const int lane = t & 31, w = t >> 5;
    const int qid = lane >> 2, t4 = lane & 3;
    const int wm = (w >> 1) * 32, wn = (w & 1) * 32;
#pragma unroll
    for (int im = 0; im < 2; im++)
#pragma unroll
        for (int in = 0; in < 4; in++)
#pragma unroll
            for (int e = 0; e < 4; e++) acc2[im][in][e] = 0.f;

#pragma unroll 4
    for (int kk = 0; kk < 256; kk += 8) {
        uint32_t af[2][4], bf[4][2];
#pragma unroll
        for (int im = 0; im < 2; im++) {
            int r = wm + im * 16 + qid, c = kk + t4;
            af[im][0] = __float_as_uint(hS[HW(r, c)]);   // already tf32-rounded
            af[im][1] = __float_as_uint(hS[HW(r + 8, c)]);
            af[im][2] = __float_as_uint(hS[HW(r, c + 4)]);
            af[im][3] = __float_as_uint(hS[HW(r + 8, c + 4)]);
        }
#pragma unroll
        for (int in = 0; in < 4; in++) {
            int nn = wn + in * 8 + qid, k = kk + t4;
            bf[in][0] = f2tf(Ws[k * 72 + nn]);
            bf[in][1] = f2tf(Ws[(k + 4) * 72 + nn]);
        }
#pragma unroll
        for (int im = 0; im < 2; im++)
#pragma unroll
            for (int in = 0; in < 4; in++)
                mma8(acc2[im][in], af[im], bf[in]);
    }
}

// ---------------------------------------------------------------------------
// fused per-(node, 128-batch-tile) kernel: V path then A path; Q = V + A
// ---------------------------------------------------------------------------
__global__ void __launch_bounds__(256, 1)
critic_gemm(const float* __restrict__ obs, const float* __restrict__ act,
            const float* __restrict__ VW1, const float* __restrict__ Vb1,
            const float* __restrict__ VW2, const float* __restrict__ Vb2,
            const float* __restrict__ AW1, const float* __restrict__ Ab1,
            const float* __restrict__ AW2, const float* __restrict__ Ab2)
{
    extern __shared__ float sm[];
    float* hS  = sm;
    float* stg = sm + 32768;
    float* b1S = sm + 32768 + 24576;
    float* b2S = b1S + 256;

    const int n  = (int)blockIdx.y;
    const int b0 = (int)blockIdx.x * 128;
    const int t  = threadIdx.x;
    const int lane = t & 31, w = t >> 5;
    const int qid = lane >> 2, t4 = lane & 3;
    const int wm2 = (w >> 1) * 32, wn2 = (w & 1) * 32;

    // ---- V path ----
    b1S[t] = Vb1[n * Hdim + t];
    if (t < Fdim) b2S[t] = Vb2[n * Fdim + t];
    __syncthreads();

    layer1(hS, stg, b1S, obs, obs,
           VW1 + (size_t)n * Hdim * Hdim, VW2 + (size_t)n * Hdim * Fdim, 8, n, b0);
    __syncthreads();

    float vacc[2][4][4];
    layer2(hS, stg, vacc);

    // write V (+b2) to Q scratch
#pragma unroll
    for (int im = 0; im < 2; im++)
#pragma unroll
        for (int in = 0; in < 4; in++) {
            int r = wm2 + im * 16 + qid;
            int c = wn2 + in * 8 + t4 * 2;
            size_t base0 = ((size_t)(b0 + r) * Ndim + n) * Fdim + c;
            size_t base1 = ((size_t)(b0 + r + 8) * Ndim + n) * Fdim + c;
            g_Q[base0]     = vacc[im][in][0] + b2S[c];
            g_Q[base0 + 1] = vacc[im][in][1] + b2S[c + 1];
            g_Q[base1]     = vacc[im][in][2] + b2S[c];
            g_Q[base1 + 1] = vacc[im][in][3] + b2S[c + 1];
        }
    __syncthreads();   // all stg/hS reads done before A path overwrites them

    // ---- A path ----
    b1S[t] = Ab1[n * Hdim + t];
    if (t < Fdim) b2S[t] = Ab2[n * Fdim + t];
    __syncthreads();

    layer1(hS, stg, b1S, obs, act,
           AW1 + (size_t)n * 2 * Hdim * Hdim, AW2 + (size_t)n * Hdim * Fdim, 16, n, b0);
    __syncthreads();

    float aacc[2][4][4];
    layer2(hS, stg, aacc);

    // Q = V + A (+b2): read-modify-write (same thread wrote these addresses)
#pragma unroll
    for (int im = 0; im < 2; im++)
#pragma unroll
        for (int in = 0; in < 4; in++) {
            int r = wm2 + im * 16 + qid;
            int c = wn2 + in * 8 + t4 * 2;
            size_t base0 = ((size_t)(b0 + r) * Ndim + n) * Fdim + c;
            size_t base1 = ((size_t)(b0 + r + 8) * Ndim + n) * Fdim + c;
            g_Q[base0]     += aacc[im][in][0] + b2S[c];
            g_Q[base0 + 1] += aacc[im][in][1] + b2S[c + 1];
            g_Q[base1]     += aacc[im][in][2] + b2S[c];
            g_Q[base1 + 1] += aacc[im][in][3] + b2S[c + 1];
        }
}

// ---------------------------------------------------------------------------
// final: subset mins over 4 neighbors (15 subsets), chi = sum_s w[n,s]*min_s,
// out[b,n] = mean_f(chi_f + Q[b, center(n), f]).
// block (64 f-lanes, 4 batches), grid (N, B/4). Handles int32 or int64 edges.
// ---------------------------------------------------------------------------
__global__ void critic_final(const float* __restrict__ chi_m,
                             const int* __restrict__ e32,
                             float* __restrict__ out)
{
    const int n  = (int)blockIdx.x;
    const int tx = threadIdx.x;            // 0..63 : feature
    const int ty = threadIdx.y;            // 0..3  : batch sub
    const int b  = (int)blockIdx.y * 4 + ty;
    const int t  = ty * 64 + tx;

    __shared__ float wS[15];
    __shared__ int   nd[5];
    __shared__ float part[8];

    // dtype detect: int32 layout -> word[5] = centers[1] = 1; int64 -> 0.
    const bool is64 = (e32[5] != 1);

    if (t < 15)
        wS[t] = (chi_m[(n * 3 + 0) * 15 + t] +
                 chi_m[(n * 3 + 1) * 15 + t] +
                 chi_m[(n * 3 + 2) * 15 + t]) * (1.f / 3.f);
    if (t < 5)
        nd[t] = is64 ? e32[n * 10 + 2 * t] : e32[n * 5 + t];
    __syncthreads();

    const float* Qb = g_Q + (size_t)b * (Ndim * Fdim);
    const float q0 = Qb[nd[1] * Fdim + tx];
    const float q1 = Qb[nd[2] * Fdim + tx];
    const float q2 = Qb[nd[3] * Fdim + tx];
    const float q3 = Qb[nd[4] * Fdim + tx];
    const float qc = Qb[nd[0] * Fdim + tx];

    // subset mins: subset value s (1..15), bit i selects neighbor i
    const float v3  = fminf(q0, q1);
    const float v5  = fminf(q0, q2);
    const float v6  = fminf(q1, q2);
    const float v7  = fminf(v3, q2);
    const float v9  = fminf(q0, q3);
    const float v10 = fminf(q1, q3);
    const float v11 = fminf(v3, q3);
    const float v12 = fminf(q2, q3);
    const float v13 = fminf(v5, q3);
    const float v14 = fminf(v6, q3);
    const float v15 = fminf(v7, q3);

    float chi = wS[0] * q0  + wS[1] * q1  + wS[2] * v3  + wS[3] * q2
              + wS[4] * v5  + wS[5] * v6  + wS[6] * v7  + wS[7] * q3
              + wS[8] * v9  + wS[9] * v10 + wS[10] * v11 + wS[11] * v12
              + wS[12] * v13 + wS[13] * v14 + wS[14] * v15;

    float r = (chi + qc) * (1.f / 64.f);
#pragma unroll
    for (int o = 16; o; o >>= 1)
        r += __shfl_xor_sync(0xffffffffu, r, o);

    const int warp = t >> 5;               // 0..7
    if ((t & 31) == 0) part[warp] = r;
    __syncthreads();
    if (tx == 0)
        out[b * Ndim + n] = part[ty * 2] + part[ty * 2 + 1];
}

// ---------------------------------------------------------------------------
// no-op kernels: pad the launch stream so ncu (-s 5 -c 1) captures critic_gemm
// (launch #5 = second launch of the first graph replay).
// ---------------------------------------------------------------------------
__global__ void nop_a() {}
__global__ void nop_b() {}

// ---------------------------------------------------------------------------
extern "C" void kernel_launch(void* const* d_in, const int* in_sizes, int n_in,
                              void* d_out, int out_size)
{
    const float* obs = (const float*)d_in[0];
    const float* act = (const float*)d_in[1];
    const float* VW1 = (const float*)d_in[2];
    const float* Vb1 = (const float*)d_in[3];
    const float* VW2 = (const float*)d_in[4];
    const float* Vb2 = (const float*)d_in[5];
    const float* AW1 = (const float*)d_in[6];
    const float* Ab1 = (const float*)d_in[7];
    const float* AW2 = (const float*)d_in[8];
    const float* Ab2 = (const float*)d_in[9];
    const float* chi = (const float*)d_in[10];
    const int*   edg = (const int*)d_in[11];

    cudaFuncSetAttribute(critic_gemm,
                         cudaFuncAttributeMaxDynamicSharedMemorySize, SMEM_BYTES);

    nop_a<<<1, 32>>>();

    critic_gemm<<<dim3(Bdim / 128, Ndim), 256, SMEM_BYTES>>>(
        obs, act, VW1, Vb1, VW2, Vb2, AW1, Ab1, AW2, Ab2);

    critic_final<<<dim3(Ndim, Bdim / 4), dim3(64, 4)>>>(
        chi, edg, (float*)d_out);

    nop_b<<<1, 32>>>();
}